// round 1
// baseline (speedup 1.0000x reference)
#include <cuda_runtime.h>
#include <cstdint>

// DetectionLayer: x (16, 255, 76, 76) f32 -> out (16, 17328, 85) f32
// out[b, a*5776 + gy*76 + gx, c]:
//   c==0: (sigmoid(x0)+gx)*8
//   c==1: (sigmoid(x1)+gy)*8
//   c==2: exp(x2)*anchor_w[a]   (anchor_w scaled back by stride -> raw anchor)
//   c==3: exp(x3)*anchor_h[a]
//   c>=4: sigmoid(xc)
// where x_c = x[b, a*85+c, gy, gx]; stride = 608/76 = 8.

#define NG   76
#define NA   3
#define NCH  85          // 5 + 80
#define PAD  77          // smem row stride (gcd(77,32)=1 -> conflict-free transpose)

__global__ __launch_bounds__(256)
void detection_layer_kernel(const float* __restrict__ x, float* __restrict__ out) {
    const int gy = blockIdx.x;   // 0..75
    const int a  = blockIdx.y;   // 0..2
    const int b  = blockIdx.z;   // 0..15

    __shared__ float tile[NCH * PAD];

    // raw anchors (scaled_anchor * stride == raw anchor)
    const float aw = (a == 0) ? 10.0f : (a == 1 ? 16.0f : 33.0f);
    const float ah = (a == 0) ? 13.0f : (a == 1 ? 30.0f : 23.0f);

    // input base for (b, a*85 + 0, gy, 0)
    const float* src = x + ((size_t)(b * (NA * NCH) + a * NCH) * NG + gy) * NG;

    const float fgy = (float)gy;

    // Phase 1: coalesced load along gx (channel rows are 5776 floats apart),
    // transform in-flight, store to smem[c][gx].
    for (int idx = threadIdx.x; idx < NCH * NG; idx += blockDim.x) {
        const int c  = idx / NG;
        const int gx = idx - c * NG;
        const float v = src[(size_t)c * (NG * NG) + gx];

        float r;
        if (c == 2) {
            r = __expf(v) * aw;
        } else if (c == 3) {
            r = __expf(v) * ah;
        } else {
            const float s = 1.0f / (1.0f + __expf(-v));
            if (c == 0)      r = (s + (float)gx) * 8.0f;
            else if (c == 1) r = (s + fgy) * 8.0f;
            else             r = s;
        }
        tile[c * PAD + gx] = r;
    }
    __syncthreads();

    // Phase 2: output tile for this (b,a,gy) is 76*85 = 6460 CONTIGUOUS floats.
    // Fully coalesced stores; transposed smem reads are conflict-free via PAD=77.
    float* dst = out + ((size_t)b * (NA * NG * NG) + a * (NG * NG) + gy * NG) * (size_t)NCH;
    for (int idx = threadIdx.x; idx < NG * NCH; idx += blockDim.x) {
        const int s = idx / NCH;          // local gx
        const int c = idx - s * NCH;      // channel
        dst[idx] = tile[c * PAD + s];
    }
}

extern "C" void kernel_launch(void* const* d_in, const int* in_sizes, int n_in,
                              void* d_out, int out_size) {
    const float* x = (const float*)d_in[0];
    float* out = (float*)d_out;
    dim3 grid(NG, NA, 16);
    detection_layer_kernel<<<grid, 256>>>(x, out);
}

// round 2
// speedup vs baseline: 1.6634x; 1.6634x over previous
#include <cuda_runtime.h>
#include <cstdint>

// DetectionLayer: x (16, 255, 76, 76) f32 -> out (16, 17328, 85) f32
// out[b, a*5776 + gy*76 + gx, c]:
//   c==0: (sigmoid(x0)+gx)*8
//   c==1: (sigmoid(x1)+gy)*8
//   c==2: exp(x2)*10/16/33 (per anchor a)
//   c==3: exp(x3)*13/30/23
//   c>=4: sigmoid(xc)
// x_c = x[b, a*85+c, gy, gx]; stride = 608/76 = 8.

#define NG    76
#define NGV   19          // float4s per grid row
#define NA    3
#define NCH   85
#define PAD   77          // smem row stride in floats
#define NVEC1 (NCH * NGV) // 1615 float4 loads per block
#define NVEC2 ((NG * NCH) / 4) // 1615 float4 stores per block

__device__ __forceinline__ float fsig(float v) {
    return __fdividef(1.0f, 1.0f + __expf(-v));
}

__global__ __launch_bounds__(256)
void detection_layer_kernel(const float* __restrict__ x, float* __restrict__ out) {
    const int gy = blockIdx.x;   // 0..75
    const int a  = blockIdx.y;   // 0..2
    const int b  = blockIdx.z;   // 0..15

    __shared__ float tile[NCH * PAD];

    const float aw = (a == 0) ? 10.0f : (a == 1 ? 16.0f : 33.0f);
    const float ah = (a == 0) ? 13.0f : (a == 1 ? 30.0f : 23.0f);
    const float fgy = (float)gy;

    // input base for (b, a*85 + 0, gy, 0): multiple of 76 floats -> 16B aligned
    const float* src = x + ((size_t)(b * (NA * NCH) + a * NCH) * NG + gy) * NG;

    // ---- Phase 1: float4 loads along gx, transform, scalar smem stores ----
    {
        int v = threadIdx.x;             // float4 index in [0, 1615)
        int c = v / NGV;                 // channel (one div, once)
        int g = v - c * NGV;             // float4 pos within row
        #pragma unroll 1
        for (; v < NVEC1; v += 256) {
            const float4 in = *reinterpret_cast<const float4*>(
                src + (size_t)c * (NG * NG) + (g << 2));
            float4 o;
            if (c >= 4) {
                o.x = fsig(in.x); o.y = fsig(in.y);
                o.z = fsig(in.z); o.w = fsig(in.w);
            } else if (c == 0) {
                const float gx0 = (float)(g << 2);
                o.x = (fsig(in.x) + gx0)        * 8.0f;
                o.y = (fsig(in.y) + gx0 + 1.0f) * 8.0f;
                o.z = (fsig(in.z) + gx0 + 2.0f) * 8.0f;
                o.w = (fsig(in.w) + gx0 + 3.0f) * 8.0f;
            } else if (c == 1) {
                o.x = (fsig(in.x) + fgy) * 8.0f;
                o.y = (fsig(in.y) + fgy) * 8.0f;
                o.z = (fsig(in.z) + fgy) * 8.0f;
                o.w = (fsig(in.w) + fgy) * 8.0f;
            } else {
                const float an = (c == 2) ? aw : ah;
                o.x = __expf(in.x) * an; o.y = __expf(in.y) * an;
                o.z = __expf(in.z) * an; o.w = __expf(in.w) * an;
            }
            float* t = &tile[c * PAD + (g << 2)];
            t[0] = o.x; t[1] = o.y; t[2] = o.z; t[3] = o.w;

            // v += 256  ==>  c += 13, g += 9  (256 = 13*19 + 9)
            c += 13; g += 9;
            if (g >= NGV) { g -= NGV; ++c; }
        }
    }
    __syncthreads();

    // ---- Phase 2: gather from smem, float4 coalesced stores ----
    // Block's output chunk: 6460 contiguous floats (16B-aligned base).
    float* dst = out + ((size_t)b * (NA * NG * NG) + a * (NG * NG) + gy * NG) * (size_t)NCH;
    {
        int v = threadIdx.x;             // float4 index in [0, 1615)
        int lin = v << 2;
        int s = lin / NCH;               // spatial pos (one div, once)
        int c = lin - s * NCH;           // channel
        #pragma unroll 1
        for (; v < NVEC2; v += 256) {
            int cc = c, ss = s;
            float4 o;
            o.x = tile[cc * PAD + ss]; if (++cc == NCH) { cc = 0; ++ss; }
            o.y = tile[cc * PAD + ss]; if (++cc == NCH) { cc = 0; ++ss; }
            o.z = tile[cc * PAD + ss]; if (++cc == NCH) { cc = 0; ++ss; }
            o.w = tile[cc * PAD + ss];
            *reinterpret_cast<float4*>(dst + ((size_t)v << 2)) = o;

            // lin += 1024  ==>  s += 12, c += 4  (1024 = 12*85 + 4)
            s += 12; c += 4;
            if (c >= NCH) { c -= NCH; ++s; }
        }
    }
}

extern "C" void kernel_launch(void* const* d_in, const int* in_sizes, int n_in,
                              void* d_out, int out_size) {
    const float* x = (const float*)d_in[0];
    float* out = (float*)d_out;
    dim3 grid(NG, NA, 16);
    detection_layer_kernel<<<grid, 256>>>(x, out);
}

// round 3
// speedup vs baseline: 1.8029x; 1.0839x over previous
#include <cuda_runtime.h>
#include <cstdint>

// DetectionLayer: x (16, 255, 76, 76) f32 -> out (16, 17328, 85) f32
// out[b, a*5776 + gy*76 + gx, c]:
//   c==0: (sigmoid(x0)+gx)*8 ; c==1: (sigmoid(x1)+gy)*8
//   c==2: exp(x2)*aw[a]      ; c==3: exp(x3)*ah[a]
//   c>=4: sigmoid(xc)
// x_c = x[b, a*85+c, gy, gx]; stride = 608/76 = 8.

#define NG    76
#define NGV   19            // float4s per grid row
#define NA    3
#define NCH   85
#define TILE_F (NG * NCH)   // 6460 floats = block's contiguous output chunk
#define NVEC  (TILE_F / 4)  // 1615 float4s

__device__ __forceinline__ float fsig(float v) {
    return __fdividef(1.0f, 1.0f + __expf(-v));
}

__global__ __launch_bounds__(256)
void detection_layer_kernel(const float* __restrict__ x, float* __restrict__ out) {
    const int gy = blockIdx.x;   // 0..75
    const int a  = blockIdx.y;   // 0..2
    const int b  = blockIdx.z;   // 0..15

    // smem tile holds the output chunk in FINAL layout: tile[s*85 + c]
    __shared__ float tile[TILE_F];

    const float aw = (a == 0) ? 10.0f : (a == 1 ? 16.0f : 33.0f);
    const float ah = (a == 0) ? 13.0f : (a == 1 ? 30.0f : 23.0f);
    const float fgy = (float)gy;

    // input base for (b, a*85 + 0, gy, 0): multiple of 76 floats -> 16B aligned
    const float* src = x + ((size_t)(b * (NA * NCH) + a * NCH) * NG + gy) * NG;

    // ---- Phase 1: coalesced float4 loads, transform, scatter to smem ----
    {
        int v = threadIdx.x;             // float4 index in [0, 1615)
        int c = v / NGV;                 // channel (one div, once)
        int g = v - c * NGV;             // float4 pos within grid row
        #pragma unroll 1
        for (; v < NCH * NGV; v += 256) {
            const float4 in = *reinterpret_cast<const float4*>(
                src + (size_t)c * (NG * NG) + (g << 2));
            float4 o;
            if (c >= 4) {
                o.x = fsig(in.x); o.y = fsig(in.y);
                o.z = fsig(in.z); o.w = fsig(in.w);
            } else if (c == 0) {
                const float gx0 = (float)(g << 2);
                o.x = (fsig(in.x) + gx0)        * 8.0f;
                o.y = (fsig(in.y) + gx0 + 1.0f) * 8.0f;
                o.z = (fsig(in.z) + gx0 + 2.0f) * 8.0f;
                o.w = (fsig(in.w) + gx0 + 3.0f) * 8.0f;
            } else if (c == 1) {
                o.x = (fsig(in.x) + fgy) * 8.0f;
                o.y = (fsig(in.y) + fgy) * 8.0f;
                o.z = (fsig(in.z) + fgy) * 8.0f;
                o.w = (fsig(in.w) + fgy) * 8.0f;
            } else {
                const float an = (c == 2) ? aw : ah;
                o.x = __expf(in.x) * an; o.y = __expf(in.y) * an;
                o.z = __expf(in.z) * an; o.w = __expf(in.w) * an;
            }
            // scatter into output-layout tile: tile[(4g+k)*85 + c]
            float* t = &tile[(g << 2) * NCH + c];
            t[0]       = o.x;
            t[NCH]     = o.y;
            t[2 * NCH] = o.z;
            t[3 * NCH] = o.w;

            // v += 256  ==>  c += 13, g += 9  (256 = 13*19 + 9)
            c += 13; g += 9;
            if (g >= NGV) { g -= NGV; ++c; }
        }
    }
    __syncthreads();

    // ---- Phase 2: pure vector copy smem -> gmem (no index math) ----
    float* dst = out + ((size_t)b * (NA * NG * NG) + a * (NG * NG) + gy * NG) * (size_t)NCH;
    float4* __restrict__ dst4 = reinterpret_cast<float4*>(dst);
    const float4* __restrict__ s4 = reinterpret_cast<const float4*>(tile);
    #pragma unroll 2
    for (int i = threadIdx.x; i < NVEC; i += 256) {
        dst4[i] = s4[i];
    }
}

extern "C" void kernel_launch(void* const* d_in, const int* in_sizes, int n_in,
                              void* d_out, int out_size) {
    const float* x = (const float*)d_in[0];
    float* out = (float*)d_out;
    dim3 grid(NG, NA, 16);
    detection_layer_kernel<<<grid, 256>>>(x, out);
}

// round 4
// speedup vs baseline: 1.8131x; 1.0056x over previous
#include <cuda_runtime.h>
#include <cstdint>

// DetectionLayer: x (16, 255, 76, 76) f32 -> out (16, 17328, 85) f32
// out[b, a*5776 + gy*76 + gx, c]:
//   c==0: (sigmoid(x0)+gx)*8 ; c==1: (sigmoid(x1)+gy)*8
//   c==2: exp(x2)*aw[a]      ; c==3: exp(x3)*ah[a]
//   c>=4: sigmoid(xc)
// x_c = x[b, a*85+c, gy, gx]; stride = 608/76 = 8.

#define NG    76
#define NGG   (NG * NG)     // 5776
#define NGV   19            // float4s per grid row
#define NA    3
#define NCH   85
#define TILE_F (NG * NCH)   // 6460 floats = block's contiguous output chunk
#define NVEC  (TILE_F / 4)  // 1615 float4s

__device__ __forceinline__ float fsig(float v) {
    return __fdividef(1.0f, 1.0f + __expf(-v));
}

__device__ __forceinline__ void xform_store(
    float4 in, int c, int g, float aw, float ah, float fgy,
    float* __restrict__ tile)
{
    float4 o;
    if (c >= 4) {
        o.x = fsig(in.x); o.y = fsig(in.y);
        o.z = fsig(in.z); o.w = fsig(in.w);
    } else if (c == 0) {
        const float gx0 = (float)(g << 2);
        o.x = (fsig(in.x) + gx0)        * 8.0f;
        o.y = (fsig(in.y) + gx0 + 1.0f) * 8.0f;
        o.z = (fsig(in.z) + gx0 + 2.0f) * 8.0f;
        o.w = (fsig(in.w) + gx0 + 3.0f) * 8.0f;
    } else if (c == 1) {
        o.x = (fsig(in.x) + fgy) * 8.0f;
        o.y = (fsig(in.y) + fgy) * 8.0f;
        o.z = (fsig(in.z) + fgy) * 8.0f;
        o.w = (fsig(in.w) + fgy) * 8.0f;
    } else {
        const float an = (c == 2) ? aw : ah;
        o.x = __expf(in.x) * an; o.y = __expf(in.y) * an;
        o.z = __expf(in.z) * an; o.w = __expf(in.w) * an;
    }
    // scatter into output-layout tile: tile[(4g+k)*85 + c]
    float* t = &tile[(g << 2) * NCH + c];
    t[0]       = o.x;
    t[NCH]     = o.y;
    t[2 * NCH] = o.z;
    t[3 * NCH] = o.w;
}

__global__ __launch_bounds__(256)
void detection_layer_kernel(const float* __restrict__ x, float* __restrict__ out) {
    const int tid = threadIdx.x;
    const int gy = blockIdx.x;   // 0..75
    const int a  = blockIdx.y;   // 0..2
    const int b  = blockIdx.z;   // 0..15

    // smem tile holds the output chunk in FINAL layout: tile[s*85 + c]
    __shared__ float tile[TILE_F];

    const float aw = (a == 0) ? 10.0f : (a == 1 ? 16.0f : 33.0f);
    const float ah = (a == 0) ? 13.0f : (a == 1 ? 30.0f : 23.0f);
    const float fgy = (float)gy;

    // input base for (b, a*85 + 0, gy, 0): multiple of 76 floats -> 16B aligned
    const float* src = x + ((size_t)(b * (NA * NCH) + a * NCH) * NG + gy) * NG;

    // ---- Phase 1: paired (MLP=2) coalesced loads, transform, scatter ----
    // 1615 = 3*512 + 79 : three paired rounds + tail.
    #pragma unroll 1
    for (int base = 0; base < 1536; base += 512) {
        const int v0 = base + tid;
        const int v1 = v0 + 256;
        const int c0 = v0 / NGV, g0 = v0 - c0 * NGV;
        const int c1 = v1 / NGV, g1 = v1 - c1 * NGV;
        // issue both loads before any transform (MLP = 2)
        const float4 a0 = *reinterpret_cast<const float4*>(
            src + (size_t)c0 * NGG + (g0 << 2));
        const float4 a1 = *reinterpret_cast<const float4*>(
            src + (size_t)c1 * NGG + (g1 << 2));
        xform_store(a0, c0, g0, aw, ah, fgy, tile);
        xform_store(a1, c1, g1, aw, ah, fgy, tile);
    }
    {
        const int v = 1536 + tid;
        if (v < NVEC) {
            const int c = v / NGV, g = v - c * NGV;
            const float4 a0 = *reinterpret_cast<const float4*>(
                src + (size_t)c * NGG + (g << 2));
            xform_store(a0, c, g, aw, ah, fgy, tile);
        }
    }
    __syncthreads();

    // ---- Phase 2: vector copy smem -> gmem, unrolled x3 ----
    float* dst = out + ((size_t)b * (NA * NGG) + a * NGG + gy * NG) * (size_t)NCH;
    float4* __restrict__ dst4 = reinterpret_cast<float4*>(dst);
    const float4* __restrict__ s4 = reinterpret_cast<const float4*>(tile);
    #pragma unroll 1
    for (int base = 0; base < 1536; base += 768) {
        const int i0 = base + tid;
        const float4 q0 = s4[i0];
        const float4 q1 = s4[i0 + 256];
        const float4 q2 = s4[i0 + 512];
        dst4[i0]       = q0;
        dst4[i0 + 256] = q1;
        dst4[i0 + 512] = q2;
    }
    {
        const int i = 1536 + tid;
        if (i < NVEC) dst4[i] = s4[i];
    }
}

extern "C" void kernel_launch(void* const* d_in, const int* in_sizes, int n_in,
                              void* d_out, int out_size) {
    const float* x = (const float*)d_in[0];
    float* out = (float*)d_out;
    dim3 grid(NG, NA, 16);
    detection_layer_kernel<<<grid, 256>>>(x, out);
}